// round 1
// baseline (speedup 1.0000x reference)
#include <cuda_runtime.h>
#include <math.h>

#define BB 128
#define SS 200
#define QQ 20000
#define VV 128
#define KK 128
#define CC 64
#define SUMD 128
#define NROWS (BB*SS)
#define TILE_R 32
#define PRE_THREADS 320

// Scratch: precomputed per-(b,s) erase gates, add vectors, softmax weights.
__device__ float g_E[(size_t)NROWS * VV];
__device__ float g_A[(size_t)NROWS * VV];
__device__ float g_Wt[(size_t)NROWS * CC];

// ---------------------------------------------------------------------------
// Kernel A: fused precompute.
//   For each row (b,s):
//     iv = i_emb[input]            (128)
//     E  = sigmoid(iv @ erase_W + erase_b)     (128)
//     A  = tanh   (iv @ add_W   + add_b)       (128)
//     W  = softmax(q_emb[qid] @ key_memory)    (64)
// 320 threads: t<128 -> erase col t, t<256 -> add col t-128, t<320 -> key col.
// Each thread accumulates 32 rows (the CTA's tile); A-operands in smem,
// weight columns streamed from L2 (weights total 160 KB, L2-resident).
// ---------------------------------------------------------------------------
__global__ __launch_bounds__(PRE_THREADS) void precompute_kernel(
    const float* __restrict__ q_emb,
    const float* __restrict__ i_emb,
    const float* __restrict__ key_memory,
    const float* __restrict__ erase_W,
    const float* __restrict__ erase_b,
    const float* __restrict__ add_W,
    const float* __restrict__ add_b,
    const int*   __restrict__ input)
{
    __shared__ float sIV[TILE_R][KK];
    __shared__ float sQK[TILE_R][KK];
    __shared__ float sLg[TILE_R][CC + 1];   // +1 pad: conflict-free row reads
    __shared__ int   sIdx[TILE_R];

    const int row0 = blockIdx.x * TILE_R;
    const int t = threadIdx.x;

    if (t < TILE_R) sIdx[t] = input[row0 + t];
    __syncthreads();

    for (int i = t; i < TILE_R * KK; i += PRE_THREADS) {
        int r = i >> 7, k = i & 127;
        int idx = sIdx[r];
        sIV[r][k] = i_emb[(size_t)idx * VV + k];
        int qid = idx > QQ ? idx - QQ : idx;
        sQK[r][k] = q_emb[(size_t)qid * KK + k];
    }
    __syncthreads();

    const float* Wp;
    int stride;
    float bias = 0.f;
    const float (*sA)[KK];
    if (t < 128)      { Wp = erase_W + t;            stride = VV; bias = erase_b[t];       sA = sIV; }
    else if (t < 256) { Wp = add_W + (t - 128);      stride = VV; bias = add_b[t - 128];   sA = sIV; }
    else              { Wp = key_memory + (t - 256); stride = CC;                          sA = sQK; }

    float acc[TILE_R];
#pragma unroll
    for (int r = 0; r < TILE_R; r++) acc[r] = bias;

#pragma unroll 2
    for (int k = 0; k < KK; k++) {
        float w = __ldg(Wp + k * stride);
#pragma unroll
        for (int r = 0; r < TILE_R; r++)
            acc[r] = fmaf(sA[r][k], w, acc[r]);
    }

    if (t < 128) {
#pragma unroll
        for (int r = 0; r < TILE_R; r++)
            g_E[(size_t)(row0 + r) * VV + t] = 1.f / (1.f + __expf(-acc[r]));
    } else if (t < 256) {
        const int c = t - 128;
#pragma unroll
        for (int r = 0; r < TILE_R; r++)
            g_A[(size_t)(row0 + r) * VV + c] = tanhf(acc[r]);
    } else {
        const int c = t - 256;
#pragma unroll
        for (int r = 0; r < TILE_R; r++)
            sLg[r][c] = acc[r];
    }
    __syncthreads();

    // Row softmax over C=64 (one thread per row).
    if (t < TILE_R) {
        const int r = t;
        float mx = -1e30f;
#pragma unroll
        for (int c = 0; c < CC; c++) mx = fmaxf(mx, sLg[r][c]);
        float sum = 0.f;
#pragma unroll
        for (int c = 0; c < CC; c++) { float e = __expf(sLg[r][c] - mx); sLg[r][c] = e; sum += e; }
        const float inv = 1.f / sum;
        float* dst = g_Wt + (size_t)(row0 + r) * CC;
#pragma unroll
        for (int c = 0; c < CC; c++) dst[c] = sLg[r][c] * inv;
    }
}

// ---------------------------------------------------------------------------
// Kernel B: sequential scan over S=200 + final readout. One CTA per batch.
// 256 threads; each owns a 4(v) x 8(c) register tile of the 128x64 memory.
// Per step: mem = mem + w[c] * (a[v] - mem*e[v])  -> 2 FMA/element.
// e/a/w staged via double-buffered smem with register prefetch; ONE barrier
// per step (write goes to the buffer everyone finished reading last step).
// ---------------------------------------------------------------------------
__global__ __launch_bounds__(256) void scan_kernel(
    const float* __restrict__ q_emb,
    const float* __restrict__ key_memory,
    const float* __restrict__ init_value_memory,
    const float* __restrict__ summ_W,
    const float* __restrict__ summ_b,
    const float* __restrict__ out_W,
    const float* __restrict__ out_b,
    const int*   __restrict__ target_id,
    float* __restrict__ out)
{
    const int b  = blockIdx.x;
    const int t  = threadIdx.x;
    const int vg = t >> 3;   // 0..31  -> v rows [4*vg, 4*vg+4)
    const int cg = t & 7;    // 0..7   -> c cols [8*cg, 8*cg+8)

    __shared__ float sE[2][VV];
    __shared__ float sAd[2][VV];
    __shared__ float sW[2][CC];

    float m[32];
#pragma unroll
    for (int jv = 0; jv < 4; jv++)
#pragma unroll
        for (int jc = 0; jc < 8; jc++)
            m[jv * 8 + jc] = init_value_memory[(vg * 4 + jv) * CC + cg * 8 + jc];

    const float* pE = g_E  + (size_t)b * SS * VV;
    const float* pA = g_A  + (size_t)b * SS * VV;
    const float* pW = g_Wt + (size_t)b * SS * CC;

    // Prologue: stage step 0 into buffer 0.
    float rE = 0.f, rA = 0.f, rW = 0.f;
    if (t < 128)      { rE = pE[t]; rA = pA[t]; }
    else if (t < 192) { rW = pW[t - 128]; }
    if (t < 128)      { sE[0][t] = rE; sAd[0][t] = rA; }
    else if (t < 192) { sW[0][t - 128] = rW; }
    __syncthreads();

    for (int s = 0; s < SS; s++) {
        const int p = s & 1;
        // Prefetch step s+1 into registers (overlaps with compute below).
        if (s + 1 < SS) {
            const float* nE = pE + (size_t)(s + 1) * VV;
            const float* nA = pA + (size_t)(s + 1) * VV;
            const float* nW = pW + (size_t)(s + 1) * CC;
            if (t < 128)      { rE = nE[t]; rA = nA[t]; }
            else if (t < 192) { rW = nW[t - 128]; }
        }

        float ev[4], av[4], wv[8];
#pragma unroll
        for (int j = 0; j < 4; j++) { ev[j] = sE[p][vg * 4 + j]; av[j] = sAd[p][vg * 4 + j]; }
#pragma unroll
        for (int j = 0; j < 8; j++) wv[j] = sW[p][cg * 8 + j];

#pragma unroll
        for (int jv = 0; jv < 4; jv++)
#pragma unroll
            for (int jc = 0; jc < 8; jc++) {
                const int i = jv * 8 + jc;
                m[i] = fmaf(wv[jc], fmaf(-m[i], ev[jv], av[jv]), m[i]);
            }

        if (s + 1 < SS) {
            if (t < 128)      { sE[p ^ 1][t] = rE; sAd[p ^ 1][t] = rA; }
            else if (t < 192) { sW[p ^ 1][t - 128] = rW; }
        }
        __syncthreads();
    }

    // ---- Final readout ----
    __shared__ float sMem[VV][CC + 1];   // padded: row reads conflict-free
#pragma unroll
    for (int jv = 0; jv < 4; jv++)
#pragma unroll
        for (int jc = 0; jc < 8; jc++)
            sMem[vg * 4 + jv][cg * 8 + jc] = m[jv * 8 + jc];

    __shared__ float sQv[KK];
    __shared__ float sWt[CC];
    __shared__ float sCat[VV + KK];
    __shared__ float sSum[SUMD];

    const int tgt = target_id[b];
    if (t < KK) sQv[t] = q_emb[(size_t)tgt * KK + t];
    __syncthreads();

    if (t < CC) {
        float a2 = 0.f;
#pragma unroll 4
        for (int k = 0; k < KK; k++)
            a2 = fmaf(sQv[k], __ldg(key_memory + k * CC + t), a2);
        sWt[t] = a2;
    }
    __syncthreads();

    if (t == 0) {
        float mx = -1e30f;
        for (int c = 0; c < CC; c++) mx = fmaxf(mx, sWt[c]);
        float sum = 0.f;
        for (int c = 0; c < CC; c++) { float e = __expf(sWt[c] - mx); sWt[c] = e; sum += e; }
        const float inv = 1.f / sum;
        for (int c = 0; c < CC; c++) sWt[c] *= inv;
    }
    __syncthreads();

    if (t < VV) {
        float a2 = 0.f;
#pragma unroll
        for (int c = 0; c < CC; c++)
            a2 = fmaf(sMem[t][c], sWt[c], a2);
        sCat[t] = a2;                    // read part
    } else {
        sCat[VV + (t - 128)] = sQv[t - 128];   // qv part
    }
    __syncthreads();

    if (t < SUMD) {
        float a2 = summ_b[t];
#pragma unroll 4
        for (int j = 0; j < VV + KK; j++)
            a2 = fmaf(sCat[j], __ldg(summ_W + j * SUMD + t), a2);
        sSum[t] = tanhf(a2);
    }
    __syncthreads();

    if (t < 32) {
        float pr = 0.f;
#pragma unroll
        for (int j = 0; j < SUMD; j += 32)
            pr = fmaf(sSum[t + j], __ldg(out_W + t + j), pr);
#pragma unroll
        for (int off = 16; off > 0; off >>= 1)
            pr += __shfl_down_sync(0xffffffffu, pr, off);
        if (t == 0) out[b] = pr + out_b[0];
    }
}

// ---------------------------------------------------------------------------
extern "C" void kernel_launch(void* const* d_in, const int* in_sizes, int n_in,
                              void* d_out, int out_size)
{
    const float* q_emb      = (const float*)d_in[0];
    const float* i_emb      = (const float*)d_in[1];
    const float* key_memory = (const float*)d_in[2];
    const float* init_vm    = (const float*)d_in[3];
    const float* erase_W    = (const float*)d_in[4];
    const float* erase_b    = (const float*)d_in[5];
    const float* add_W      = (const float*)d_in[6];
    const float* add_b      = (const float*)d_in[7];
    const float* summ_W     = (const float*)d_in[8];
    const float* summ_b     = (const float*)d_in[9];
    const float* out_W      = (const float*)d_in[10];
    const float* out_b      = (const float*)d_in[11];
    const int*   input      = (const int*)d_in[12];
    const int*   target_id  = (const int*)d_in[13];
    float* out = (float*)d_out;

    precompute_kernel<<<NROWS / TILE_R, PRE_THREADS>>>(
        q_emb, i_emb, key_memory, erase_W, erase_b, add_W, add_b, input);

    scan_kernel<<<BB, 256>>>(
        q_emb, key_memory, init_vm, summ_W, summ_b, out_W, out_b, target_id, out);
}

// round 2
// speedup vs baseline: 1.7058x; 1.7058x over previous
#include <cuda_runtime.h>
#include <math.h>
#include <stdint.h>

#define BB 128
#define SS 200
#define QQ 20000
#define VV 128
#define KK 128
#define CC 64
#define SUMD 128
#define NROWS (BB*SS)
#define TILE_R 32
#define PRE_THREADS 320

// Interleaved per-(b,s) record: [negE(128) | A(128) | W(64)] = 320 floats = 1280B
#define STEPF 320
#define CH 50                      // steps per scan chunk
#define NCH (SS/CH)                // 4
#define CHBYTES (CH*STEPF*4)       // 64000
#define SMEM_DYN (2*CHBYTES + 16)  // double buffer + mbarriers

__device__ float g_pack[(size_t)NROWS * STEPF];

typedef unsigned long long ull;

// ---------------- f32x2 helpers ----------------
__device__ __forceinline__ ull fma2(ull a, ull b, ull c) {
    ull d;
    asm("fma.rn.f32x2 %0, %1, %2, %3;" : "=l"(d) : "l"(a), "l"(b), "l"(c));
    return d;
}
__device__ __forceinline__ ull pack2(float x, float y) {
    ull d;
    asm("mov.b64 %0, {%1, %2};" : "=l"(d) : "f"(x), "f"(y));
    return d;
}
__device__ __forceinline__ float2 unpack2(ull v) {
    float2 r;
    asm("mov.b64 {%0, %1}, %2;" : "=f"(r.x), "=f"(r.y) : "l"(v));
    return r;
}
__device__ __forceinline__ uint32_t smem_u32(const void* p) {
    uint32_t a;
    asm("{ .reg .u64 t; cvta.to.shared.u64 t, %1; cvt.u32.u64 %0, t; }" : "=r"(a) : "l"(p));
    return a;
}
__device__ __forceinline__ void mbar_init(uint32_t mbar, uint32_t cnt) {
    asm volatile("mbarrier.init.shared.b64 [%0], %1;" :: "r"(mbar), "r"(cnt) : "memory");
}
__device__ __forceinline__ void mbar_expect_tx(uint32_t mbar, uint32_t bytes) {
    asm volatile("mbarrier.arrive.expect_tx.shared.b64 _, [%0], %1;" :: "r"(mbar), "r"(bytes) : "memory");
}
__device__ __forceinline__ void mbar_wait(uint32_t mbar, uint32_t parity) {
    asm volatile(
        "{\n\t"
        ".reg .pred P;\n"
        "WAITLOOP_%=:\n\t"
        "mbarrier.try_wait.parity.acquire.cta.shared::cta.b64 P, [%0], %1, 0x989680;\n\t"
        "@P bra.uni WAITDONE_%=;\n\t"
        "bra.uni WAITLOOP_%=;\n"
        "WAITDONE_%=:\n\t"
        "}"
        :: "r"(mbar), "r"(parity) : "memory");
}
__device__ __forceinline__ void bulk_g2s(uint32_t dst, const void* src, uint32_t bytes, uint32_t mbar) {
    asm volatile(
        "cp.async.bulk.shared::cta.global.mbarrier::complete_tx::bytes [%0], [%1], %2, [%3];"
        :: "r"(dst), "l"(src), "r"(bytes), "r"(mbar) : "memory");
}

// ---------------------------------------------------------------------------
// Kernel A: fused precompute with f32x2 row-pair packing.
//   Writes interleaved record per (b,s): negE(128) | A(128) | W(64).
// 320 threads: t<128 -> -sigmoid(erase) col t; t<256 -> tanh(add) col t-128;
//              t<320 -> key logits col t-256 (+ row softmax by 32 threads).
// ---------------------------------------------------------------------------
__global__ __launch_bounds__(PRE_THREADS) void precompute_kernel(
    const float* __restrict__ q_emb,
    const float* __restrict__ i_emb,
    const float* __restrict__ key_memory,
    const float* __restrict__ erase_W,
    const float* __restrict__ erase_b,
    const float* __restrict__ add_W,
    const float* __restrict__ add_b,
    const int*   __restrict__ input)
{
    // sIV2[j][k] = (iv[row 2j][k], iv[row 2j+1][k]); same for sQK2.
    __shared__ float2 sIV2[TILE_R/2][KK];
    __shared__ float2 sQK2[TILE_R/2][KK];
    __shared__ float  sLg[TILE_R][CC + 1];
    __shared__ int    sIdx[TILE_R];

    const int row0 = blockIdx.x * TILE_R;
    const int t = threadIdx.x;

    if (t < TILE_R) sIdx[t] = input[row0 + t];
    __syncthreads();

    for (int i = t; i < TILE_R * KK; i += PRE_THREADS) {
        int r = i >> 7, k = i & 127;
        int idx = sIdx[r];
        float iv = i_emb[(size_t)idx * VV + k];
        int qid = idx > QQ ? idx - QQ : idx;
        float qe = q_emb[(size_t)qid * KK + k];
        ((float*)&sIV2[r >> 1][k])[r & 1] = iv;
        ((float*)&sQK2[r >> 1][k])[r & 1] = qe;
    }
    __syncthreads();

    const float* Wp;
    int stride;
    float bias = 0.f;
    const float2 (*sm)[KK];
    if (t < 128)      { Wp = erase_W + t;            stride = VV; bias = erase_b[t];      sm = sIV2; }
    else if (t < 256) { Wp = add_W + (t - 128);      stride = VV; bias = add_b[t - 128];  sm = sIV2; }
    else              { Wp = key_memory + (t - 256); stride = CC;                         sm = sQK2; }

    ull acc2[TILE_R/2];
    const ull b2 = pack2(bias, bias);
#pragma unroll
    for (int j = 0; j < TILE_R/2; j++) acc2[j] = b2;

#pragma unroll 2
    for (int k = 0; k < KK; k += 2) {
        float wa = __ldg(Wp + k * stride);
        float wb = __ldg(Wp + (k + 1) * stride);
        ull w2a = pack2(wa, wa);
        ull w2b = pack2(wb, wb);
#pragma unroll
        for (int j = 0; j < TILE_R/2; j++) {
            ulonglong2 u = *(const ulonglong2*)&sm[j][k];   // LDS.128: 2 k's of the row pair
            acc2[j] = fma2(u.x, w2a, acc2[j]);
            acc2[j] = fma2(u.y, w2b, acc2[j]);
        }
    }

    if (t < 128) {
#pragma unroll
        for (int j = 0; j < TILE_R/2; j++) {
            float2 f = unpack2(acc2[j]);
            g_pack[(size_t)(row0 + 2*j    ) * STEPF + t] = -1.f / (1.f + __expf(-f.x));
            g_pack[(size_t)(row0 + 2*j + 1) * STEPF + t] = -1.f / (1.f + __expf(-f.y));
        }
    } else if (t < 256) {
        const int c = t - 128;
#pragma unroll
        for (int j = 0; j < TILE_R/2; j++) {
            float2 f = unpack2(acc2[j]);
            g_pack[(size_t)(row0 + 2*j    ) * STEPF + 128 + c] = tanhf(f.x);
            g_pack[(size_t)(row0 + 2*j + 1) * STEPF + 128 + c] = tanhf(f.y);
        }
    } else {
        const int c = t - 256;
#pragma unroll
        for (int j = 0; j < TILE_R/2; j++) {
            float2 f = unpack2(acc2[j]);
            sLg[2*j    ][c] = f.x;
            sLg[2*j + 1][c] = f.y;
        }
    }
    __syncthreads();

    if (t < TILE_R) {
        const int r = t;
        float mx = -1e30f;
#pragma unroll
        for (int c = 0; c < CC; c++) mx = fmaxf(mx, sLg[r][c]);
        float sum = 0.f;
#pragma unroll
        for (int c = 0; c < CC; c++) { float e = __expf(sLg[r][c] - mx); sLg[r][c] = e; sum += e; }
        const float inv = 1.f / sum;
        float* dst = g_pack + (size_t)(row0 + r) * STEPF + 256;
#pragma unroll
        for (int c = 0; c < CC; c++) dst[c] = sLg[r][c] * inv;
    }
}

// ---------------------------------------------------------------------------
// Kernel B: scan + readout. One CTA per batch, 512 threads.
// Each thread owns a 4(v) x 4(c) tile, packed along v into 8 f32x2 regs.
// Steps are staged in 50-step chunks via cp.async.bulk (double-buffered):
// ZERO barriers inside a chunk.
// Per step: m = m + w[c] * (a[v] + m*negE[v])   -> 16 FMA2 per thread.
// ---------------------------------------------------------------------------
__global__ __launch_bounds__(512) void scan_kernel(
    const float* __restrict__ q_emb,
    const float* __restrict__ key_memory,
    const float* __restrict__ init_value_memory,
    const float* __restrict__ summ_W,
    const float* __restrict__ summ_b,
    const float* __restrict__ out_W,
    const float* __restrict__ out_b,
    const int*   __restrict__ target_id,
    float* __restrict__ out)
{
    extern __shared__ __align__(16) float dsm[];
    __shared__ float sQv[KK];
    __shared__ float sWt[CC];
    __shared__ float sCat[VV + KK];
    __shared__ float sSum[SUMD];

    const int b  = blockIdx.x;
    const int t  = threadIdx.x;
    const int vg = t >> 4;    // 0..31 -> v rows [4*vg, 4*vg+4)
    const int cg = t & 15;    // 0..15 -> c cols [4*cg, 4*cg+4)

    const uint32_t mb0 = smem_u32(dsm + 2 * CH * STEPF);
    const uint32_t mb1 = mb0 + 8;

    if (t == 0) {
        mbar_init(mb0, 1);
        mbar_init(mb1, 1);
        asm volatile("fence.proxy.async.shared::cta;" ::: "memory");
    }
    __syncthreads();

    // Load initial memory: m2[q*4+jc] = (mem[vg*4+2q][cg*4+jc], mem[vg*4+2q+1][...])
    ull m2[8];
#pragma unroll
    for (int q = 0; q < 2; q++) {
        const float4 ra = *(const float4*)(init_value_memory + (vg*4 + 2*q    ) * CC + cg*4);
        const float4 rb = *(const float4*)(init_value_memory + (vg*4 + 2*q + 1) * CC + cg*4);
        m2[q*4 + 0] = pack2(ra.x, rb.x);
        m2[q*4 + 1] = pack2(ra.y, rb.y);
        m2[q*4 + 2] = pack2(ra.z, rb.z);
        m2[q*4 + 3] = pack2(ra.w, rb.w);
    }

    const char* gsrc = (const char*)(g_pack + (size_t)b * SS * STEPF);
    if (t == 0) {
        mbar_expect_tx(mb0, CHBYTES);
        bulk_g2s(smem_u32(dsm), gsrc, CHBYTES, mb0);
    }

    int ph0 = 0, ph1 = 0;
    for (int kc = 0; kc < NCH; kc++) {
        const int p = kc & 1;
        if (p == 0) { mbar_wait(mb0, ph0); ph0 ^= 1; }
        else        { mbar_wait(mb1, ph1); ph1 ^= 1; }
        __syncthreads();   // all threads done reading the buffer we're about to refill
        if (t == 0 && kc + 1 < NCH) {
            const uint32_t mbn = (p == 0) ? mb1 : mb0;
            mbar_expect_tx(mbn, CHBYTES);
            bulk_g2s(smem_u32(dsm) + (p ^ 1) * CHBYTES, gsrc + (size_t)(kc + 1) * CHBYTES,
                     CHBYTES, mbn);
        }

        const float* base = dsm + p * CH * STEPF;
#pragma unroll 2
        for (int s = 0; s < CH; s++) {
            const float* sp = base + s * STEPF;
            const float4 e4 = *(const float4*)(sp + vg * 4);          // negE
            const float4 a4 = *(const float4*)(sp + 128 + vg * 4);
            const float4 w4 = *(const float4*)(sp + 256 + cg * 4);
            const ull ne2[2] = { pack2(e4.x, e4.y), pack2(e4.z, e4.w) };
            const ull a2 [2] = { pack2(a4.x, a4.y), pack2(a4.z, a4.w) };
            const ull w2 [4] = { pack2(w4.x, w4.x), pack2(w4.y, w4.y),
                                 pack2(w4.z, w4.z), pack2(w4.w, w4.w) };
#pragma unroll
            for (int q = 0; q < 2; q++)
#pragma unroll
                for (int jc = 0; jc < 4; jc++) {
                    const int i = q * 4 + jc;
                    ull tt = fma2(m2[i], ne2[q], a2[q]);   // a - m*e  (e stored negated)
                    m2[i] = fma2(w2[jc], tt, m2[i]);       // m + w*(a - m*e)
                }
        }
    }

    // ---- Final readout (reuse dsm as sMem[128][65]) ----
    __syncthreads();
    float* sMem = dsm;   // [v*65 + c]
#pragma unroll
    for (int q = 0; q < 2; q++)
#pragma unroll
        for (int jc = 0; jc < 4; jc++) {
            float2 f = unpack2(m2[q*4 + jc]);
            const int v0 = vg*4 + 2*q, c = cg*4 + jc;
            sMem[(v0    ) * 65 + c] = f.x;
            sMem[(v0 + 1) * 65 + c] = f.y;
        }

    const int tgt = target_id[b];
    if (t < KK) sQv[t] = q_emb[(size_t)tgt * KK + t];
    __syncthreads();

    if (t < CC) {
        float a2s = 0.f;
#pragma unroll 4
        for (int k = 0; k < KK; k++)
            a2s = fmaf(sQv[k], __ldg(key_memory + k * CC + t), a2s);
        sWt[t] = a2s;
    }
    __syncthreads();

    if (t == 0) {
        float mx = -1e30f;
        for (int c = 0; c < CC; c++) mx = fmaxf(mx, sWt[c]);
        float sum = 0.f;
        for (int c = 0; c < CC; c++) { float e = __expf(sWt[c] - mx); sWt[c] = e; sum += e; }
        const float inv = 1.f / sum;
        for (int c = 0; c < CC; c++) sWt[c] *= inv;
    }
    __syncthreads();

    if (t < VV) {
        float a2s = 0.f;
#pragma unroll
        for (int c = 0; c < CC; c++)
            a2s = fmaf(sMem[t * 65 + c], sWt[c], a2s);
        sCat[t] = a2s;
    } else if (t < 256) {
        sCat[VV + (t - 128)] = sQv[t - 128];
    }
    __syncthreads();

    if (t < SUMD) {
        float a2s = summ_b[t];
#pragma unroll 4
        for (int j = 0; j < VV + KK; j++)
            a2s = fmaf(sCat[j], __ldg(summ_W + j * SUMD + t), a2s);
        sSum[t] = tanhf(a2s);
    }
    __syncthreads();

    if (t < 32) {
        float pr = 0.f;
#pragma unroll
        for (int j = 0; j < SUMD; j += 32)
            pr = fmaf(sSum[t + j], __ldg(out_W + t + j), pr);
#pragma unroll
        for (int off = 16; off > 0; off >>= 1)
            pr += __shfl_down_sync(0xffffffffu, pr, off);
        if (t == 0) out[b] = pr + out_b[0];
    }
}

// ---------------------------------------------------------------------------
extern "C" void kernel_launch(void* const* d_in, const int* in_sizes, int n_in,
                              void* d_out, int out_size)
{
    const float* q_emb      = (const float*)d_in[0];
    const float* i_emb      = (const float*)d_in[1];
    const float* key_memory = (const float*)d_in[2];
    const float* init_vm    = (const float*)d_in[3];
    const float* erase_W    = (const float*)d_in[4];
    const float* erase_b    = (const float*)d_in[5];
    const float* add_W      = (const float*)d_in[6];
    const float* add_b      = (const float*)d_in[7];
    const float* summ_W     = (const float*)d_in[8];
    const float* summ_b     = (const float*)d_in[9];
    const float* out_W      = (const float*)d_in[10];
    const float* out_b      = (const float*)d_in[11];
    const int*   input      = (const int*)d_in[12];
    const int*   target_id  = (const int*)d_in[13];
    float* out = (float*)d_out;

    cudaFuncSetAttribute(scan_kernel, cudaFuncAttributeMaxDynamicSharedMemorySize, SMEM_DYN);

    precompute_kernel<<<NROWS / TILE_R, PRE_THREADS>>>(
        q_emb, i_emb, key_memory, erase_W, erase_b, add_W, add_b, input);

    scan_kernel<<<BB, 512, SMEM_DYN>>>(
        q_emb, key_memory, init_vm, summ_W, summ_b, out_W, out_b, target_id, out);
}

// round 3
// speedup vs baseline: 1.9114x; 1.1206x over previous
#include <cuda_runtime.h>
#include <math.h>
#include <stdint.h>

#define BB 128
#define SS 200
#define QQ 20000
#define VV 128
#define KK 128
#define CC 64
#define SUMD 128
#define NROWS (BB*SS)

// Interleaved per-(b,s) record: [negE(128) | A(128) | W(64)] = 320 floats
#define STEPF 320
#define CH 50
#define NCH (SS/CH)
#define CHBYTES (CH*STEPF*4)
#define SCAN_SMEM (2*CHBYTES + 16)

// precompute geometry
#define PROWS 64
#define PT 640
#define KCH 16                      // k per chunk
#define NKCH (KK/KCH)               // 8
#define WCH_E (KCH*VV*4)            // 8192 B
#define WCH_K (KCH*CC*4)            // 4096 B
#define WCH_TOT (2*WCH_E + WCH_K)   // 20480 B
// dyn smem: sIV(32K) sQK(32K) sWE[2](16K) sWA[2](16K) sWK[2](8K) mbar
#define OFF_QK   (PROWS*KK)
#define OFF_WE   (2*PROWS*KK)
#define OFF_WA   (OFF_WE + 2*KCH*VV)
#define OFF_WK   (OFF_WA + 2*KCH*VV)
#define OFF_MB   (OFF_WK + 2*KCH*CC)
#define PRE_SMEM ((OFF_MB + 4)*4)

__device__ float g_pack[(size_t)NROWS * STEPF];

typedef unsigned long long ull;

__device__ __forceinline__ ull fma2(ull a, ull b, ull c) {
    ull d;
    asm("fma.rn.f32x2 %0, %1, %2, %3;" : "=l"(d) : "l"(a), "l"(b), "l"(c));
    return d;
}
__device__ __forceinline__ ull pack2(float x, float y) {
    ull d;
    asm("mov.b64 %0, {%1, %2};" : "=l"(d) : "f"(x), "f"(y));
    return d;
}
__device__ __forceinline__ float2 unpack2(ull v) {
    float2 r;
    asm("mov.b64 {%0, %1}, %2;" : "=f"(r.x), "=f"(r.y) : "l"(v));
    return r;
}
__device__ __forceinline__ uint32_t smem_u32(const void* p) {
    uint32_t a;
    asm("{ .reg .u64 t; cvta.to.shared.u64 t, %1; cvt.u32.u64 %0, t; }" : "=r"(a) : "l"(p));
    return a;
}
__device__ __forceinline__ void mbar_init(uint32_t mbar, uint32_t cnt) {
    asm volatile("mbarrier.init.shared.b64 [%0], %1;" :: "r"(mbar), "r"(cnt) : "memory");
}
__device__ __forceinline__ void mbar_expect_tx(uint32_t mbar, uint32_t bytes) {
    asm volatile("mbarrier.arrive.expect_tx.shared.b64 _, [%0], %1;" :: "r"(mbar), "r"(bytes) : "memory");
}
__device__ __forceinline__ void mbar_wait(uint32_t mbar, uint32_t parity) {
    asm volatile(
        "{\n\t.reg .pred P;\n"
        "WAITLOOP_%=:\n\t"
        "mbarrier.try_wait.parity.acquire.cta.shared::cta.b64 P, [%0], %1, 0x989680;\n\t"
        "@P bra.uni WAITDONE_%=;\n\t"
        "bra.uni WAITLOOP_%=;\n"
        "WAITDONE_%=:\n\t}"
        :: "r"(mbar), "r"(parity) : "memory");
}
__device__ __forceinline__ void bulk_g2s(uint32_t dst, const void* src, uint32_t bytes, uint32_t mbar) {
    asm volatile(
        "cp.async.bulk.shared::cta.global.mbarrier::complete_tx::bytes [%0], [%1], %2, [%3];"
        :: "r"(dst), "l"(src), "r"(bytes), "r"(mbar) : "memory");
}

// ---------------------------------------------------------------------------
// Kernel A: precompute as register-tiled SGEMM.
// CTA: 64 rows x 320 cols, 640 threads, thread tile 8 rows x 4 cols
// (f32x2 column-pair accumulators). Cols 0-127: -sigmoid(iv@erase_W+b);
// 128-255: tanh(iv@add_W+b); 256-319: softmax(qk@key) (softmax in epilogue).
// W streamed in k-chunks of 16, double-buffered via cp.async.bulk.
// ---------------------------------------------------------------------------
__global__ __launch_bounds__(PT) void precompute_kernel(
    const float* __restrict__ q_emb,
    const float* __restrict__ i_emb,
    const float* __restrict__ key_memory,
    const float* __restrict__ erase_W,
    const float* __restrict__ erase_b,
    const float* __restrict__ add_W,
    const float* __restrict__ add_b,
    const int*   __restrict__ input)
{
    extern __shared__ __align__(16) float psm[];
    float* sIV = psm;                 // [64][128]
    float* sQK = psm + OFF_QK;        // [64][128]
    float* sWE = psm + OFF_WE;        // [2][16][128]
    float* sWA = psm + OFF_WA;        // [2][16][128]
    float* sWK = psm + OFF_WK;        // [2][16][64]
    const uint32_t mb = smem_u32(psm + OFF_MB);

    __shared__ float sLg[PROWS][68];
    __shared__ int   sIdx[PROWS];

    const int t    = threadIdx.x;
    const int lane = t & 31;
    const int wid  = t >> 5;
    const int tc   = t % 80;          // column group (4 cols)
    const int tr   = t / 80;          // row group (8 rows)
    const int row0 = blockIdx.x * PROWS;

    if (t < PROWS) sIdx[t] = input[row0 + t];
    if (t == 0) {
        mbar_init(mb, 1);
        asm volatile("fence.proxy.async.shared::cta;" ::: "memory");
        mbar_expect_tx(mb, WCH_TOT);
        bulk_g2s(smem_u32(sWE), erase_W,    WCH_E, mb);
        bulk_g2s(smem_u32(sWA), add_W,      WCH_E, mb);
        bulk_g2s(smem_u32(sWK), key_memory, WCH_K, mb);
    }
    __syncthreads();

    // Gather embeddings: one warp per row, float4 per lane (coalesced).
    for (int r = wid; r < PROWS; r += PT/32) {
        const int idx = sIdx[r];
        const int qid = idx > QQ ? idx - QQ : idx;
        float4 v  = *((const float4*)(i_emb + (size_t)idx * VV) + lane);
        float4 qv = *((const float4*)(q_emb + (size_t)qid * KK) + lane);
        *(float4*)&sIV[r * KK + lane * 4] = v;
        *(float4*)&sQK[r * KK + lane * 4] = qv;
    }
    __syncthreads();

    // Per-thread setup
    const float* Asrc = (tc < 64) ? sIV : sQK;
    const float* Wreg;
    int wstride;
    ull bias0, bias1;
    if (tc < 32) {
        Wreg = sWE + tc * 4; wstride = VV;
        float4 b = *(const float4*)(erase_b + tc * 4);
        bias0 = pack2(b.x, b.y); bias1 = pack2(b.z, b.w);
    } else if (tc < 64) {
        Wreg = sWA + (tc - 32) * 4; wstride = VV;
        float4 b = *(const float4*)(add_b + (tc - 32) * 4);
        bias0 = pack2(b.x, b.y); bias1 = pack2(b.z, b.w);
    } else {
        Wreg = sWK + (tc - 64) * 4; wstride = CC;
        bias0 = bias1 = pack2(0.f, 0.f);
    }

    ull acc[8][2];
#pragma unroll
    for (int i = 0; i < 8; i++) { acc[i][0] = bias0; acc[i][1] = bias1; }

    for (int ch = 0; ch < NKCH; ch++) {
        const int buf = ch & 1;
        mbar_wait(mb, ch & 1);
        __syncthreads();
        if (t == 0 && ch + 1 < NKCH) {
            const int nb = buf ^ 1, k0n = (ch + 1) * KCH;
            mbar_expect_tx(mb, WCH_TOT);
            bulk_g2s(smem_u32(sWE + nb * KCH * VV), erase_W    + k0n * VV, WCH_E, mb);
            bulk_g2s(smem_u32(sWA + nb * KCH * VV), add_W      + k0n * VV, WCH_E, mb);
            bulk_g2s(smem_u32(sWK + nb * KCH * CC), key_memory + k0n * CC, WCH_K, mb);
        }

        const float* W = Wreg + buf * KCH * wstride;
        const float* A = Asrc + tr * 8 * KK + ch * KCH;
#pragma unroll
        for (int kk = 0; kk < KCH; kk += 4) {
            ulonglong2 wl[4];
#pragma unroll
            for (int j = 0; j < 4; j++)
                wl[j] = *(const ulonglong2*)(W + (kk + j) * wstride);
            float4 av[8];
#pragma unroll
            for (int i = 0; i < 8; i++)
                av[i] = *(const float4*)(A + i * KK + kk);
#pragma unroll
            for (int j = 0; j < 4; j++) {
#pragma unroll
                for (int i = 0; i < 8; i++) {
                    const float a = ((const float*)&av[i])[j];
                    const ull ad = pack2(a, a);
                    acc[i][0] = fma2(ad, wl[j].x, acc[i][0]);
                    acc[i][1] = fma2(ad, wl[j].y, acc[i][1]);
                }
            }
        }
    }

    // Epilogue
    if (tc < 32) {
#pragma unroll
        for (int i = 0; i < 8; i++) {
            const int r = row0 + tr * 8 + i;
            float2 f0 = unpack2(acc[i][0]), f1 = unpack2(acc[i][1]);
            float4 o;
            o.x = -1.f / (1.f + __expf(-f0.x));
            o.y = -1.f / (1.f + __expf(-f0.y));
            o.z = -1.f / (1.f + __expf(-f1.x));
            o.w = -1.f / (1.f + __expf(-f1.y));
            *(float4*)&g_pack[(size_t)r * STEPF + tc * 4] = o;
        }
    } else if (tc < 64) {
#pragma unroll
        for (int i = 0; i < 8; i++) {
            const int r = row0 + tr * 8 + i;
            float2 f0 = unpack2(acc[i][0]), f1 = unpack2(acc[i][1]);
            float4 o;
            o.x = tanhf(f0.x); o.y = tanhf(f0.y);
            o.z = tanhf(f1.x); o.w = tanhf(f1.y);
            *(float4*)&g_pack[(size_t)r * STEPF + 128 + (tc - 32) * 4] = o;
        }
    } else {
#pragma unroll
        for (int i = 0; i < 8; i++) {
            float2 f0 = unpack2(acc[i][0]), f1 = unpack2(acc[i][1]);
            float4 o; o.x = f0.x; o.y = f0.y; o.z = f1.x; o.w = f1.y;
            *(float4*)&sLg[tr * 8 + i][(tc - 64) * 4] = o;
        }
    }
    __syncthreads();

    if (t < PROWS) {
        float mx = -1e30f;
#pragma unroll
        for (int c = 0; c < CC; c++) mx = fmaxf(mx, sLg[t][c]);
        float sum = 0.f;
#pragma unroll
        for (int c = 0; c < CC; c++) { float e = __expf(sLg[t][c] - mx); sLg[t][c] = e; sum += e; }
        const float inv = 1.f / sum;
        float* dst = g_pack + (size_t)(row0 + t) * STEPF + 256;
#pragma unroll
        for (int c = 0; c < CC; c++) dst[c] = sLg[t][c] * inv;
    }
}

// ---------------------------------------------------------------------------
// Kernel B: scan + readout. One CTA per batch, 1024 threads.
// Thread tile 4(v) x 2(c), v-pairs packed in 4 f32x2 regs. Per step:
// 2 LDS.128 (negE,A reinterpret as pairs) + 1 LDS.64 (w) + 2 movs + 8 FMA2.
// 50-step chunks double-buffered via cp.async.bulk; no barrier inside chunk.
// ---------------------------------------------------------------------------
__global__ __launch_bounds__(1024) void scan_kernel(
    const float* __restrict__ q_emb,
    const float* __restrict__ key_memory,
    const float* __restrict__ init_value_memory,
    const float* __restrict__ summ_W,
    const float* __restrict__ summ_b,
    const float* __restrict__ out_W,
    const float* __restrict__ out_b,
    const int*   __restrict__ target_id,
    float* __restrict__ out)
{
    extern __shared__ __align__(16) float dsm[];
    __shared__ float sQv[KK];
    __shared__ float sWt[CC];
    __shared__ float sCat[VV + KK];
    __shared__ float sSum[SUMD];

    const int b  = blockIdx.x;
    const int t  = threadIdx.x;
    const int vg = t >> 5;    // 0..31 -> v rows [4*vg, 4*vg+4)
    const int cg = t & 31;    // 0..31 -> c cols [2*cg, 2*cg+2)

    const uint32_t mb0 = smem_u32(dsm + 2 * CH * STEPF);
    const uint32_t mb1 = mb0 + 8;

    if (t == 0) {
        mbar_init(mb0, 1);
        mbar_init(mb1, 1);
        asm volatile("fence.proxy.async.shared::cta;" ::: "memory");
    }
    __syncthreads();

    // m2[q*2+jc] = (mem[vg*4+2q][cg*2+jc], mem[vg*4+2q+1][cg*2+jc])
    ull m2[4];
#pragma unroll
    for (int q = 0; q < 2; q++) {
        float2 ra = *(const float2*)(init_value_memory + (vg*4 + 2*q    ) * CC + cg*2);
        float2 rb = *(const float2*)(init_value_memory + (vg*4 + 2*q + 1) * CC + cg*2);
        m2[q*2 + 0] = pack2(ra.x, rb.x);
        m2[q*2 + 1] = pack2(ra.y, rb.y);
    }

    const char* gsrc = (const char*)(g_pack + (size_t)b * SS * STEPF);
    if (t == 0) {
        mbar_expect_tx(mb0, CHBYTES);
        bulk_g2s(smem_u32(dsm), gsrc, CHBYTES, mb0);
    }

    int ph0 = 0, ph1 = 0;
    for (int kc = 0; kc < NCH; kc++) {
        const int p = kc & 1;
        if (p == 0) { mbar_wait(mb0, ph0); ph0 ^= 1; }
        else        { mbar_wait(mb1, ph1); ph1 ^= 1; }
        __syncthreads();
        if (t == 0 && kc + 1 < NCH) {
            const uint32_t mbn = (p == 0) ? mb1 : mb0;
            mbar_expect_tx(mbn, CHBYTES);
            bulk_g2s(smem_u32(dsm) + (p ^ 1) * CHBYTES, gsrc + (size_t)(kc + 1) * CHBYTES,
                     CHBYTES, mbn);
        }

        const float* base = dsm + p * CH * STEPF;
#pragma unroll 2
        for (int s = 0; s < CH; s++) {
            const float* sp = base + s * STEPF;
            const ulonglong2 ne = *(const ulonglong2*)(sp + vg * 4);        // negE v-pairs
            const ulonglong2 aa = *(const ulonglong2*)(sp + 128 + vg * 4);  // A v-pairs
            const float2 wf = *(const float2*)(sp + 256 + cg * 2);
            const ull w0 = pack2(wf.x, wf.x);
            const ull w1 = pack2(wf.y, wf.y);
            m2[0] = fma2(w0, fma2(m2[0], ne.x, aa.x), m2[0]);
            m2[1] = fma2(w1, fma2(m2[1], ne.x, aa.x), m2[1]);
            m2[2] = fma2(w0, fma2(m2[2], ne.y, aa.y), m2[2]);
            m2[3] = fma2(w1, fma2(m2[3], ne.y, aa.y), m2[3]);
        }
    }

    // ---- Final readout ----
    __syncthreads();
    float* sMem = dsm;   // [v*65 + c]
#pragma unroll
    for (int q = 0; q < 2; q++)
#pragma unroll
        for (int jc = 0; jc < 2; jc++) {
            float2 f = unpack2(m2[q*2 + jc]);
            const int v0 = vg*4 + 2*q, c = cg*2 + jc;
            sMem[(v0    ) * 65 + c] = f.x;
            sMem[(v0 + 1) * 65 + c] = f.y;
        }

    const int tgt = target_id[b];
    if (t < KK) sQv[t] = q_emb[(size_t)tgt * KK + t];
    __syncthreads();

    if (t < CC) {
        float a2s = 0.f;
#pragma unroll 4
        for (int k = 0; k < KK; k++)
            a2s = fmaf(sQv[k], __ldg(key_memory + k * CC + t), a2s);
        sWt[t] = a2s;
    }
    __syncthreads();

    if (t == 0) {
        float mx = -1e30f;
        for (int c = 0; c < CC; c++) mx = fmaxf(mx, sWt[c]);
        float sum = 0.f;
        for (int c = 0; c < CC; c++) { float e = __expf(sWt[c] - mx); sWt[c] = e; sum += e; }
        const float inv = 1.f / sum;
        for (int c = 0; c < CC; c++) sWt[c] *= inv;
    }
    __syncthreads();

    if (t < VV) {
        float a2s = 0.f;
#pragma unroll
        for (int c = 0; c < CC; c++)
            a2s = fmaf(sMem[t * 65 + c], sWt[c], a2s);
        sCat[t] = a2s;
    } else if (t < 256) {
        sCat[VV + (t - 128)] = sQv[t - 128];
    }
    __syncthreads();

    if (t < SUMD) {
        float a2s = summ_b[t];
#pragma unroll 4
        for (int j = 0; j < VV + KK; j++)
            a2s = fmaf(sCat[j], __ldg(summ_W + j * SUMD + t), a2s);
        sSum[t] = tanhf(a2s);
    }
    __syncthreads();

    if (t < 32) {
        float pr = 0.f;
#pragma unroll
        for (int j = 0; j < SUMD; j += 32)
            pr = fmaf(sSum[t + j], __ldg(out_W + t + j), pr);
#pragma unroll
        for (int off = 16; off > 0; off >>= 1)
            pr += __shfl_down_sync(0xffffffffu, pr, off);
        if (t == 0) out[b] = pr + out_b[0];
    }
}

// ---------------------------------------------------------------------------
extern "C" void kernel_launch(void* const* d_in, const int* in_sizes, int n_in,
                              void* d_out, int out_size)
{
    const float* q_emb      = (const float*)d_in[0];
    const float* i_emb      = (const float*)d_in[1];
    const float* key_memory = (const float*)d_in[2];
    const float* init_vm    = (const float*)d_in[3];
    const float* erase_W    = (const float*)d_in[4];
    const float* erase_b    = (const float*)d_in[5];
    const float* add_W      = (const float*)d_in[6];
    const float* add_b      = (const float*)d_in[7];
    const float* summ_W     = (const float*)d_in[8];
    const float* summ_b     = (const float*)d_in[9];
    const float* out_W      = (const float*)d_in[10];
    const float* out_b      = (const float*)d_in[11];
    const int*   input      = (const int*)d_in[12];
    const int*   target_id  = (const int*)d_in[13];
    float* out = (float*)d_out;

    cudaFuncSetAttribute(precompute_kernel, cudaFuncAttributeMaxDynamicSharedMemorySize, PRE_SMEM);
    cudaFuncSetAttribute(scan_kernel, cudaFuncAttributeMaxDynamicSharedMemorySize, SCAN_SMEM);

    precompute_kernel<<<NROWS / PROWS, PT, PRE_SMEM>>>(
        q_emb, i_emb, key_memory, erase_W, erase_b, add_W, add_b, input);

    scan_kernel<<<BB, 1024, SCAN_SMEM>>>(
        q_emb, key_memory, init_vm, summ_W, summ_b, out_W, out_b, target_id, out);
}